// round 2
// baseline (speedup 1.0000x reference)
#include <cuda_runtime.h>
#include <math.h>

#define NB 4096
#define T_STEPS 50
#define I_DIM 17
#define HDIM 256
#define G4 1024
#define P_STEPS 20
#define BH (NB*HDIM)

// Persistent state (ping-pong h buffers; c is owner-exclusive per CTA slice).
__device__ float g_h0[2][BH];
__device__ float g_h1[2][BH];
__device__ float g_c0[BH];
__device__ float g_c1[BH];

typedef unsigned long long ull;

__device__ __forceinline__ ull pack2(float lo, float hi){
    ull r; asm("mov.b64 %0,{%1,%2};" : "=l"(r) : "f"(lo), "f"(hi)); return r;
}
__device__ __forceinline__ void unpack2(ull v, float &lo, float &hi){
    asm("mov.b64 {%0,%1}, %2;" : "=f"(lo), "=f"(hi) : "l"(v));
}
__device__ __forceinline__ ull dup2(float a){
    ull r; asm("mov.b64 %0,{%1,%1};" : "=l"(r) : "f"(a)); return r;
}
__device__ __forceinline__ void ffma2(ull &c, ull a, ull b){
    asm("fma.rn.f32x2 %0, %1, %2, %0;" : "+l"(c) : "l"(a), "l"(b));
}

__device__ __forceinline__ float sigf(float x){ return 1.0f / (1.0f + expf(-x)); }

// One LSTM timestep for one layer:
//   gates = h_in @ w_hh^T + a_aux @ w_aux^T + (b_ih + b_hh)
//   c,h update (CTA-local).
// CTA tile: 128 batch rows x 32 hidden j (x 4 gates = 128 gate columns).
__global__ void __launch_bounds__(256, 2) lstm_step(
    const float* __restrict__ h_in,   // [NB, 256]
    const float* __restrict__ w_hh,   // [1024, 256]
    const float* __restrict__ a_aux,  // [NB, auxK] row stride aux_ld
    long aux_ld, int auxK,
    const float* __restrict__ w_aux,  // [1024, auxK]
    const float* __restrict__ b_ih, const float* __restrict__ b_hh,
    float* __restrict__ c_st,         // [NB, 256]
    float* __restrict__ h_out)        // [NB, 256]
{
    __shared__ float As[17][132];   // [k][m], padded (132) for conflict-free
    __shared__ float Ws[17][128];   // [k][n]

    const int tid = threadIdx.x;
    const int tx = tid & 15;        // n-group
    const int ty = tid >> 4;        // m-group
    const int mb = blockIdx.x * 128;
    const int jb = blockIdx.y * 32;

    // Thread owns n-values: ni in [0,8): gate = ni&3, j_local = tx + (ni>=4 ? 16 : 0)
    ull acc[8][4];  // acc[mi][p] packs (ni=2p, ni=2p+1)
    {
        float bias[8];
        #pragma unroll
        for (int ni = 0; ni < 8; ni++){
            int gate = ni & 3;
            int j = jb + tx + ((ni >= 4) ? 16 : 0);
            int wr = gate * 256 + j;
            bias[ni] = b_ih[wr] + b_hh[wr];
        }
        #pragma unroll
        for (int mi = 0; mi < 8; mi++)
            #pragma unroll
            for (int p = 0; p < 4; p++)
                acc[mi][p] = pack2(bias[2*p], bias[2*p + 1]);
    }

    for (int part = 0; part < 2; part++){
        const float* A = (part == 0) ? h_in  : a_aux;
        const float* W = (part == 0) ? w_hh  : w_aux;
        const long  lda = (part == 0) ? (long)HDIM : aux_ld;
        const int   K  = (part == 0) ? HDIM : auxK;

        if (K == HDIM){
            // Aligned fast path (lda is a multiple of 4 floats).
            for (int kb = 0; kb < HDIM; kb += 16){
                __syncthreads();
                #pragma unroll
                for (int r = 0; r < 2; r++){
                    int lin = r * 256 + tid;
                    int m = lin & 127, kg = lin >> 7;
                    float4 v = *reinterpret_cast<const float4*>(&A[(long)(mb + m) * lda + kb + kg * 4]);
                    As[kg*4+0][m] = v.x; As[kg*4+1][m] = v.y;
                    As[kg*4+2][m] = v.z; As[kg*4+3][m] = v.w;
                }
                #pragma unroll
                for (int r = 0; r < 2; r++){
                    int lin = r * 256 + tid;
                    int n = lin & 127, kg = lin >> 7;
                    int gate = n & 3, jl = n >> 2;
                    int wr = gate * 256 + jb + jl;
                    float4 v = *reinterpret_cast<const float4*>(&W[(long)wr * HDIM + kb + kg * 4]);
                    Ws[kg*4+0][n] = v.x; Ws[kg*4+1][n] = v.y;
                    Ws[kg*4+2][n] = v.z; Ws[kg*4+3][n] = v.w;
                }
                __syncthreads();
                #pragma unroll
                for (int kk = 0; kk < 16; kk++){
                    float4 a0 = *reinterpret_cast<const float4*>(&As[kk][ty * 4]);
                    float4 a1 = *reinterpret_cast<const float4*>(&As[kk][64 + ty * 4]);
                    ull b0 = *reinterpret_cast<const ull*>(&Ws[kk][tx * 4]);
                    ull b1 = *reinterpret_cast<const ull*>(&Ws[kk][tx * 4 + 2]);
                    ull b2 = *reinterpret_cast<const ull*>(&Ws[kk][64 + tx * 4]);
                    ull b3 = *reinterpret_cast<const ull*>(&Ws[kk][64 + tx * 4 + 2]);
                    float am[8] = {a0.x, a0.y, a0.z, a0.w, a1.x, a1.y, a1.z, a1.w};
                    #pragma unroll
                    for (int mi = 0; mi < 8; mi++){
                        ull ad = dup2(am[mi]);
                        ffma2(acc[mi][0], ad, b0);
                        ffma2(acc[mi][1], ad, b1);
                        ffma2(acc[mi][2], ad, b2);
                        ffma2(acc[mi][3], ad, b3);
                    }
                }
            }
        } else {
            // K = 17 (x input projection), scalar path, one tile.
            __syncthreads();
            for (int idx = tid; idx < 128 * 17; idx += 256){
                int m = idx & 127, k = idx >> 7;  // 2176/128 = 17 exact
                As[k][m] = A[(long)(mb + m) * lda + k];
            }
            for (int idx = tid; idx < 128 * 17; idx += 256){
                int n = idx & 127, k = idx >> 7;
                int gate = n & 3, jl = n >> 2;
                Ws[k][n] = W[(long)(gate * 256 + jb + jl) * 17 + k];
            }
            __syncthreads();
            #pragma unroll
            for (int kk = 0; kk < 17; kk++){
                float4 a0 = *reinterpret_cast<const float4*>(&As[kk][ty * 4]);
                float4 a1 = *reinterpret_cast<const float4*>(&As[kk][64 + ty * 4]);
                ull b0 = *reinterpret_cast<const ull*>(&Ws[kk][tx * 4]);
                ull b1 = *reinterpret_cast<const ull*>(&Ws[kk][tx * 4 + 2]);
                ull b2 = *reinterpret_cast<const ull*>(&Ws[kk][64 + tx * 4]);
                ull b3 = *reinterpret_cast<const ull*>(&Ws[kk][64 + tx * 4 + 2]);
                float am[8] = {a0.x, a0.y, a0.z, a0.w, a1.x, a1.y, a1.z, a1.w};
                #pragma unroll
                for (int mi = 0; mi < 8; mi++){
                    ull ad = dup2(am[mi]);
                    ffma2(acc[mi][0], ad, b0);
                    ffma2(acc[mi][1], ad, b1);
                    ffma2(acc[mi][2], ad, b2);
                    ffma2(acc[mi][3], ad, b3);
                }
            }
        }
    }

    // Pointwise LSTM update. acc[mi][0..1] = gates (i,f),(g,o) at j=jb+tx;
    // acc[mi][2..3] = same at j=jb+16+tx.
    #pragma unroll
    for (int mi = 0; mi < 8; mi++){
        int m = (mi < 4) ? (ty * 4 + mi) : (64 + ty * 4 + (mi - 4));
        long bg = (long)(mb + m) * HDIM;
        #pragma unroll
        for (int jj = 0; jj < 2; jj++){
            float vi, vf, vg, vo;
            unpack2(acc[mi][jj * 2 + 0], vi, vf);
            unpack2(acc[mi][jj * 2 + 1], vg, vo);
            int j = jb + tx + jj * 16;
            float c_old = c_st[bg + j];
            float c_new = sigf(vf) * c_old + sigf(vi) * tanhf(vg);
            float h_new = sigf(vo) * tanhf(c_new);
            c_st[bg + j]  = c_new;
            h_out[bg + j] = h_new;
        }
    }
}

__global__ void zero_state_kernel(){
    long idx = (long)blockIdx.x * blockDim.x + threadIdx.x;
    long stride = (long)gridDim.x * blockDim.x;
    for (long i = idx; i < BH; i += stride){
        g_h0[0][i] = 0.0f;
        g_h1[0][i] = 0.0f;
        g_c0[i] = 0.0f;
        g_c1[i] = 0.0f;
    }
}

// FC head + kinematic rollout. One thread per batch row.
__global__ void __launch_bounds__(256) final_kernel(
    const float* __restrict__ h1,
    const float* __restrict__ fc_w, const float* __restrict__ fc_b,
    const float* __restrict__ x, float* __restrict__ out)
{
    __shared__ float wfc[40 * 256];
    __shared__ float bfc[40];
    const int tid = threadIdx.x;
    for (int i = tid; i < 40 * 256; i += 256) wfc[i] = fc_w[i];
    if (tid < 40) bfc[tid] = fc_b[tid];
    __syncthreads();

    const int b = blockIdx.x * 256 + tid;
    float raw[40];
    #pragma unroll
    for (int j = 0; j < 40; j++) raw[j] = bfc[j];
    const float* hrow = h1 + (long)b * HDIM;
    for (int k = 0; k < HDIM; k++){
        float hv = hrow[k];
        #pragma unroll
        for (int j = 0; j < 40; j++) raw[j] += hv * wfc[j * 256 + k];
    }

    const long xoff = (long)b * (T_STEPS * I_DIM) + 49 * I_DIM;
    float px = x[xoff + 0], py = x[xoff + 1];
    float hy = x[xoff + 7], hx = x[xoff + 8];
    float psi = atan2f(hy, hx);
    float X = px * 1920.0f, Y = py * 1080.0f;
    const float DIAG = 2202.9071700822983f;
    float decay = 1.0f;

    #pragma unroll
    for (int p = 0; p < P_STEPS; p++){
        float sr = raw[2 * p];
        float speed = fmaxf(sr, 0.0f) + log1pf(expf(-fabsf(sr)));  // softplus
        float v = speed * DIAG;
        float w = raw[2 * p + 1] * decay;
        float psi_prev = psi;
        psi = psi + w * 0.1f;
        float s = (fabsf(w) < 0.01f) ? 1.0f : 0.0f;
        float w_safe = w + s * 0.0001f;
        float radius = v / w_safe;
        float sprev, cprev, saft, caft;
        sincosf(psi_prev, &sprev, &cprev);
        sincosf(psi, &saft, &caft);
        float dx_s = v * cprev * 0.1f;
        float dy_s = v * sprev * 0.1f;
        float dx_t = radius * (saft - sprev);
        float dy_t = -radius * (caft - cprev);
        float dx = s * dx_s + (1.0f - s) * dx_t;
        float dy = s * dy_s + (1.0f - s) * dy_t;
        X += dx; Y += dy;
        out[(long)b * 40 + 2 * p]     = X / 1920.0f;
        out[(long)b * 40 + 2 * p + 1] = Y / 1080.0f;
        decay *= 0.97f;
    }
}

extern "C" void kernel_launch(void* const* d_in, const int* in_sizes, int n_in,
                              void* d_out, int out_size)
{
    const float* x     = (const float*)d_in[0];
    const float* w_ih0 = (const float*)d_in[1];
    const float* w_hh0 = (const float*)d_in[2];
    const float* b_ih0 = (const float*)d_in[3];
    const float* b_hh0 = (const float*)d_in[4];
    const float* w_ih1 = (const float*)d_in[5];
    const float* w_hh1 = (const float*)d_in[6];
    const float* b_ih1 = (const float*)d_in[7];
    const float* b_hh1 = (const float*)d_in[8];
    const float* fc_w  = (const float*)d_in[9];
    const float* fc_b  = (const float*)d_in[10];
    float* out = (float*)d_out;

    float *h0p, *h1p, *c0p, *c1p;
    cudaGetSymbolAddress((void**)&h0p, g_h0);
    cudaGetSymbolAddress((void**)&h1p, g_h1);
    cudaGetSymbolAddress((void**)&c0p, g_c0);
    cudaGetSymbolAddress((void**)&c1p, g_c1);

    zero_state_kernel<<<512, 256>>>();

    dim3 grid(NB / 128, HDIM / 32);  // (32, 8)
    for (int t = 0; t < T_STEPS; t++){
        const float* h0_in  = h0p + (t & 1) * (long)BH;
        float*       h0_out = h0p + ((t + 1) & 1) * (long)BH;
        const float* h1_in  = h1p + (t & 1) * (long)BH;
        float*       h1_out = h1p + ((t + 1) & 1) * (long)BH;

        // Layer 0: gates = h0_in @ w_hh0^T + x_t @ w_ih0^T + bias
        lstm_step<<<grid, 256>>>(h0_in, w_hh0,
                                 x + (long)t * I_DIM, (long)T_STEPS * I_DIM, I_DIM, w_ih0,
                                 b_ih0, b_hh0, c0p, h0_out);
        // Layer 1: gates = h1_in @ w_hh1^T + h0_out @ w_ih1^T + bias
        lstm_step<<<grid, 256>>>(h1_in, w_hh1,
                                 h0_out, (long)HDIM, HDIM, w_ih1,
                                 b_ih1, b_hh1, c1p, h1_out);
    }

    // After 50 steps (even), final h1 lives in buffer 0.
    final_kernel<<<NB / 256, 256>>>(h1p, fc_w, fc_b, x, out);
}

// round 14
// speedup vs baseline: 2.1541x; 2.1541x over previous
#include <cuda_runtime.h>
#include <cuda_bf16.h>
#include <math.h>
#include <stdint.h>

#define NB 4096
#define T_STEPS 50
#define I_DIM 17
#define HDIM 256
#define P_STEPS 20
#define BH (NB*HDIM)
#define XK 64
// smem: 2 buffers x (A 128x72bf16 + B 128x72bf16) = 2*36864
#define ABUF_B 18432
#define BUF_B  36864
#define SMEM_DYN 73728

// ---------------- persistent device state ----------------
__device__ __nv_bfloat16 g_h0_hi[2][BH], g_h0_lo[2][BH];
__device__ __nv_bfloat16 g_h1_hi[2][BH], g_h1_lo[2][BH];
__device__ float g_h1_f32[BH];
__device__ float g_c0[BH], g_c1[BH];
// weights split + column-permuted (see perm_row below)
__device__ __nv_bfloat16 g_w0_hi[1024*HDIM],  g_w0_lo[1024*HDIM];
__device__ __nv_bfloat16 g_wx0_hi[1024*XK],   g_wx0_lo[1024*XK];
__device__ __nv_bfloat16 g_w1h_hi[1024*HDIM], g_w1h_lo[1024*HDIM];
__device__ __nv_bfloat16 g_w1x_hi[1024*HDIM], g_w1x_lo[1024*HDIM];
__device__ float g_b0[1024], g_b1[1024];     // ORIGINAL order: gate*256 + j
__device__ __nv_bfloat16 g_xp_hi[(long)T_STEPS*NB*XK], g_xp_lo[(long)T_STEPS*NB*XK];

__device__ __forceinline__ uint32_t smem_to_u32(const void* p) {
    uint32_t a;
    asm("{ .reg .u64 t; cvta.to.shared.u64 t, %1; cvt.u32.u64 %0, t; }" : "=r"(a) : "l"(p));
    return a;
}
__device__ __forceinline__ float sigf(float x){ return 1.0f / (1.0f + expf(-x)); }
__device__ __forceinline__ void bsplit(float x, __nv_bfloat16 &hi, __nv_bfloat16 &lo){
    hi = __float2bfloat16(x);
    lo = __float2bfloat16(x - __bfloat162float(hi));
}

// Column permutation: within each 64-col tile, l = b*8 + 2q + r maps to
//   j_local = q*4 + (b&3), gate = ((b>>2)<<1) | r.
// So thread q owns (cols 2q,2q+1 of each n8 block) = 4 consecutive j x 4 gates.
__device__ __forceinline__ int perm_row(int npr){
    int tile = npr >> 6, l = npr & 63;
    int b = l >> 3, q = (l >> 1) & 3, r = l & 1;
    int j = tile * 16 + q * 4 + (b & 3);
    int gate = ((b >> 2) << 1) | r;
    return gate * 256 + j;
}

#define LDSM_X4(r0,r1,r2,r3,addr) \
    asm volatile("ldmatrix.sync.aligned.m8n8.x4.shared.b16 {%0,%1,%2,%3}, [%4];" \
        : "=r"(r0),"=r"(r1),"=r"(r2),"=r"(r3) : "r"(addr))

#define MMA_BF16(c, a0,a1,a2,a3, b0,b1) \
    asm volatile("mma.sync.aligned.m16n8k16.row.col.f32.bf16.bf16.f32 " \
        "{%0,%1,%2,%3}, {%4,%5,%6,%7}, {%8,%9}, {%0,%1,%2,%3};" \
        : "+f"((c)[0]),"+f"((c)[1]),"+f"((c)[2]),"+f"((c)[3]) \
        : "r"(a0),"r"(a1),"r"(a2),"r"(a3), "r"(b0),"r"(b1))

#define CP_ASYNC16(dst, src) \
    asm volatile("cp.async.cg.shared.global [%0], [%1], 16;" :: "r"(dst), "l"(src))
#define CP_COMMIT() asm volatile("cp.async.commit_group;")

// ---------------- mma.sync LSTM step ----------------
// gates[4096, 1024perm] = A1@W1^T + A2@W2^T via split-bf16 3-pass, then LSTM pointwise.
__global__ void __launch_bounds__(256, 2) lstm_step_mma(
    const __nv_bfloat16* __restrict__ a1_hi, const __nv_bfloat16* __restrict__ a1_lo, int nch1,
    const __nv_bfloat16* __restrict__ a2_hi, const __nv_bfloat16* __restrict__ a2_lo, int nch2, int lda2,
    const __nv_bfloat16* __restrict__ w1_hi, const __nv_bfloat16* __restrict__ w1_lo,
    const __nv_bfloat16* __restrict__ w2_hi, const __nv_bfloat16* __restrict__ w2_lo, int ldw2,
    const float* __restrict__ bias, float* __restrict__ c_st,
    __nv_bfloat16* __restrict__ hhi, __nv_bfloat16* __restrict__ hlo, float* __restrict__ hf32)
{
    extern __shared__ char sm[];
    const int tid  = threadIdx.x;
    const int lane = tid & 31, wid = tid >> 5;
    const int wm = wid & 3, wn = wid >> 2;        // warp tile: (wm*32, wn*64)
    const int mb = blockIdx.x * 128, nbT = blockIdx.y * 128;
    const uint32_t smbase = smem_to_u32(sm);

    const int per = nch1 + nch2;
    const int total = 3 * per;

    float acc[2][8][4];
    #pragma unroll
    for (int i = 0; i < 2; ++i)
        #pragma unroll
        for (int j = 0; j < 8; ++j)
            #pragma unroll
            for (int k = 0; k < 4; ++k) acc[i][j][k] = 0.0f;

    // chunk loader (8x cp.async.16B per thread + commit)
    auto load_chunk = [&](int c, uint32_t smA){
        int pass = c / per, w = c % per;
        bool p2 = (w >= nch1);
        int kb = (p2 ? (w - nch1) : w) * 64;
        const __nv_bfloat16* A = p2 ? (pass == 2 ? a2_lo : a2_hi) : (pass == 2 ? a1_lo : a1_hi);
        const __nv_bfloat16* W = p2 ? (pass == 1 ? w2_lo : w2_hi) : (pass == 1 ? w1_lo : w1_hi);
        long lda = p2 ? lda2 : HDIM;
        long ldw = p2 ? ldw2 : HDIM;
        uint32_t smB = smA + ABUF_B;
        #pragma unroll
        for (int it = 0; it < 4; ++it){
            int idx = it * 256 + tid;
            int row = idx >> 3, seg = idx & 7;
            const void* g = A + (long)(mb + row) * lda + kb + seg * 8;
            CP_ASYNC16(smA + row * 144 + seg * 16, g);
        }
        #pragma unroll
        for (int it = 0; it < 4; ++it){
            int idx = it * 256 + tid;
            int row = idx >> 3, seg = idx & 7;
            const void* g = W + (long)(nbT + row) * ldw + kb + seg * 8;
            CP_ASYNC16(smB + row * 144 + seg * 16, g);
        }
        CP_COMMIT();
    };

    load_chunk(0, smbase);

    for (int c = 0; c < total; ++c){
        uint32_t Abuf = smbase + (c & 1) * BUF_B;
        uint32_t Bbuf = Abuf + ABUF_B;
        if (c + 1 < total){
            load_chunk(c + 1, smbase + ((c + 1) & 1) * BUF_B);
            asm volatile("cp.async.wait_group 1;");
        } else {
            asm volatile("cp.async.wait_group 0;");
        }
        __syncthreads();

        uint32_t aAddr = Abuf + (uint32_t)((wm * 32 + (lane & 15)) * 144 + (lane >> 4) * 16);
        uint32_t bAddr = Bbuf + (uint32_t)((wn * 64 + ((lane >> 4) << 3) + (lane & 7)) * 144
                                           + (((lane >> 3) & 1) << 4));
        #pragma unroll
        for (int k16 = 0; k16 < 4; ++k16){
            uint32_t ak = aAddr + k16 * 32;
            uint32_t bk = bAddr + k16 * 32;
            uint32_t a[2][4];
            LDSM_X4(a[0][0], a[0][1], a[0][2], a[0][3], ak);
            LDSM_X4(a[1][0], a[1][1], a[1][2], a[1][3], ak + 16 * 144);
            uint32_t b[4][4];
            #pragma unroll
            for (int b2 = 0; b2 < 4; ++b2)
                LDSM_X4(b[b2][0], b[b2][1], b[b2][2], b[b2][3], bk + (uint32_t)(b2 * 16 * 144));
            #pragma unroll
            for (int mi = 0; mi < 2; ++mi)
                #pragma unroll
                for (int b2 = 0; b2 < 4; ++b2){
                    MMA_BF16(acc[mi][2*b2],   a[mi][0], a[mi][1], a[mi][2], a[mi][3], b[b2][0], b[b2][1]);
                    MMA_BF16(acc[mi][2*b2+1], a[mi][0], a[mi][1], a[mi][2], a[mi][3], b[b2][2], b[b2][3]);
                }
        }
        __syncthreads();
    }

    // ---------- epilogue: bias + LSTM pointwise, all gate-local ----------
    const int q = lane & 3, rgrp = lane >> 2;
    const int j0 = ((nbT + wn * 64) >> 2) + q * 4;
    float4 bi = *(const float4*)(bias +       j0);
    float4 bf = *(const float4*)(bias + 256 + j0);
    float4 bg = *(const float4*)(bias + 512 + j0);
    float4 bo = *(const float4*)(bias + 768 + j0);
    const float bI[4] = {bi.x, bi.y, bi.z, bi.w};
    const float bF[4] = {bf.x, bf.y, bf.z, bf.w};
    const float bG[4] = {bg.x, bg.y, bg.z, bg.w};
    const float bO[4] = {bo.x, bo.y, bo.z, bo.w};

    #pragma unroll
    for (int mi = 0; mi < 2; ++mi){
        #pragma unroll
        for (int rr = 0; rr < 2; ++rr){
            int m = mb + wm * 32 + mi * 16 + rgrp + rr * 8;
            long base = (long)m * HDIM + j0;
            float4 c4 = *(const float4*)(c_st + base);
            float cold[4] = {c4.x, c4.y, c4.z, c4.w};
            float cn[4], hn[4];
            #pragma unroll
            for (int jj = 0; jj < 4; ++jj){
                float gi = acc[mi][jj    ][rr*2    ] + bI[jj];
                float gf = acc[mi][jj    ][rr*2 + 1] + bF[jj];
                float gg = acc[mi][jj + 4][rr*2    ] + bG[jj];
                float go = acc[mi][jj + 4][rr*2 + 1] + bO[jj];
                float cc = sigf(gf) * cold[jj] + sigf(gi) * tanhf(gg);
                cn[jj] = cc;
                hn[jj] = sigf(go) * tanhf(cc);
            }
            *(float4*)(c_st + base) = make_float4(cn[0], cn[1], cn[2], cn[3]);

            union { __nv_bfloat162 b2[2]; unsigned long long u; } Hh, Hl;
            __nv_bfloat16 h0, l0, h1, l1;
            bsplit(hn[0], h0, l0); bsplit(hn[1], h1, l1);
            Hh.b2[0] = __halves2bfloat162(h0, h1); Hl.b2[0] = __halves2bfloat162(l0, l1);
            bsplit(hn[2], h0, l0); bsplit(hn[3], h1, l1);
            Hh.b2[1] = __halves2bfloat162(h0, h1); Hl.b2[1] = __halves2bfloat162(l0, l1);
            *(unsigned long long*)(hhi + base) = Hh.u;
            *(unsigned long long*)(hlo + base) = Hl.u;
            if (hf32)
                *(float4*)(hf32 + base) = make_float4(hn[0], hn[1], hn[2], hn[3]);
        }
    }
}

// ---------------- prep / zero ----------------
__global__ void prep_weights(
    const float* __restrict__ w_hh0, const float* __restrict__ w_ih0,
    const float* __restrict__ w_hh1, const float* __restrict__ w_ih1,
    const float* __restrict__ b_ih0, const float* __restrict__ b_hh0,
    const float* __restrict__ b_ih1, const float* __restrict__ b_hh1)
{
    int idx0 = blockIdx.x * blockDim.x + threadIdx.x;
    int stride = gridDim.x * blockDim.x;
    for (int i = idx0; i < 1024 * HDIM; i += stride){
        int npr = i >> 8, k = i & 255;
        int r = perm_row(npr);
        bsplit(w_hh0[r * 256 + k], g_w0_hi[i],  g_w0_lo[i]);
        bsplit(w_hh1[r * 256 + k], g_w1h_hi[i], g_w1h_lo[i]);
        bsplit(w_ih1[r * 256 + k], g_w1x_hi[i], g_w1x_lo[i]);
    }
    for (int i = idx0; i < 1024 * XK; i += stride){
        int npr = i >> 6, k = i & 63;
        int r = perm_row(npr);
        float v = (k < I_DIM) ? w_ih0[r * I_DIM + k] : 0.0f;
        bsplit(v, g_wx0_hi[i], g_wx0_lo[i]);
    }
    for (int i = idx0; i < 1024; i += stride){
        g_b0[i] = b_ih0[i] + b_hh0[i];   // original order
        g_b1[i] = b_ih1[i] + b_hh1[i];
    }
}

__global__ void prep_x(const float* __restrict__ x)
{
    long idx0 = (long)blockIdx.x * blockDim.x + threadIdx.x;
    long stride = (long)gridDim.x * blockDim.x;
    const long total = (long)T_STEPS * NB * XK;
    for (long i = idx0; i < total; i += stride){
        int k = (int)(i & 63);
        long r = i >> 6;
        int m = (int)(r & (NB - 1));
        int t = (int)(r >> 12);
        float v = (k < I_DIM) ? x[(long)m * (T_STEPS * I_DIM) + t * I_DIM + k] : 0.0f;
        bsplit(v, g_xp_hi[i], g_xp_lo[i]);
    }
}

__global__ void zero_state_kernel(){
    long idx = (long)blockIdx.x * blockDim.x + threadIdx.x;
    long stride = (long)gridDim.x * blockDim.x;
    const __nv_bfloat16 z = __float2bfloat16(0.0f);
    for (long i = idx; i < BH; i += stride){
        g_c0[i] = 0.0f; g_c1[i] = 0.0f;
        g_h0_hi[0][i] = z; g_h0_lo[0][i] = z;
        g_h1_hi[0][i] = z; g_h1_lo[0][i] = z;
    }
}

// ---------------- FC head + kinematic rollout ----------------
__global__ void __launch_bounds__(256) final_kernel(
    const float* __restrict__ h1,
    const float* __restrict__ fc_w, const float* __restrict__ fc_b,
    const float* __restrict__ x, float* __restrict__ out)
{
    __shared__ float wfc[40 * 256];
    __shared__ float bfc[40];
    const int tid = threadIdx.x;
    for (int i = tid; i < 40 * 256; i += 256) wfc[i] = fc_w[i];
    if (tid < 40) bfc[tid] = fc_b[tid];
    __syncthreads();

    const int b = blockIdx.x * 256 + tid;
    float raw[40];
    #pragma unroll
    for (int j = 0; j < 40; j++) raw[j] = bfc[j];
    const float* hrow = h1 + (long)b * HDIM;
    for (int k = 0; k < HDIM; k++){
        float hv = hrow[k];
        #pragma unroll
        for (int j = 0; j < 40; j++) raw[j] += hv * wfc[j * 256 + k];
    }

    const long xoff = (long)b * (T_STEPS * I_DIM) + 49 * I_DIM;
    float px = x[xoff + 0], py = x[xoff + 1];
    float hy = x[xoff + 7], hx = x[xoff + 8];
    float psi = atan2f(hy, hx);
    float X = px * 1920.0f, Y = py * 1080.0f;
    const float DIAG = 2202.9071700822983f;
    float decay = 1.0f;

    #pragma unroll
    for (int p = 0; p < P_STEPS; p++){
        float sr = raw[2 * p];
        float speed = fmaxf(sr, 0.0f) + log1pf(expf(-fabsf(sr)));
        float v = speed * DIAG;
        float w = raw[2 * p + 1] * decay;
        float psi_prev = psi;
        psi = psi + w * 0.1f;
        float s = (fabsf(w) < 0.01f) ? 1.0f : 0.0f;
        float w_safe = w + s * 0.0001f;
        float radius = v / w_safe;
        float sprev, cprev, saft, caft;
        sincosf(psi_prev, &sprev, &cprev);
        sincosf(psi, &saft, &caft);
        float dx = s * (v * cprev * 0.1f) + (1.0f - s) * (radius * (saft - sprev));
        float dy = s * (v * sprev * 0.1f) + (1.0f - s) * (-radius * (caft - cprev));
        X += dx; Y += dy;
        out[(long)b * 40 + 2 * p]     = X / 1920.0f;
        out[(long)b * 40 + 2 * p + 1] = Y / 1080.0f;
        decay *= 0.97f;
    }
}

// ---------------- host launch ----------------
extern "C" void kernel_launch(void* const* d_in, const int* in_sizes, int n_in,
                              void* d_out, int out_size)
{
    const float* x     = (const float*)d_in[0];
    const float* w_ih0 = (const float*)d_in[1];
    const float* w_hh0 = (const float*)d_in[2];
    const float* b_ih0 = (const float*)d_in[3];
    const float* b_hh0 = (const float*)d_in[4];
    const float* w_ih1 = (const float*)d_in[5];
    const float* w_hh1 = (const float*)d_in[6];
    const float* b_ih1 = (const float*)d_in[7];
    const float* b_hh1 = (const float*)d_in[8];
    const float* fc_w  = (const float*)d_in[9];
    const float* fc_b  = (const float*)d_in[10];
    float* out = (float*)d_out;

    cudaFuncSetAttribute(lstm_step_mma, cudaFuncAttributeMaxDynamicSharedMemorySize, SMEM_DYN);

    void* p;
    #define SYM(T, v, s) cudaGetSymbolAddress(&p, s); T* v = (T*)p
    SYM(__nv_bfloat16, h0hi, g_h0_hi);  SYM(__nv_bfloat16, h0lo, g_h0_lo);
    SYM(__nv_bfloat16, h1hi, g_h1_hi);  SYM(__nv_bfloat16, h1lo, g_h1_lo);
    SYM(float, h1f, g_h1_f32);
    SYM(float, c0, g_c0);               SYM(float, c1, g_c1);
    SYM(__nv_bfloat16, w0h, g_w0_hi);   SYM(__nv_bfloat16, w0l, g_w0_lo);
    SYM(__nv_bfloat16, wx0h, g_wx0_hi); SYM(__nv_bfloat16, wx0l, g_wx0_lo);
    SYM(__nv_bfloat16, w1hh, g_w1h_hi); SYM(__nv_bfloat16, w1hl, g_w1h_lo);
    SYM(__nv_bfloat16, w1xh, g_w1x_hi); SYM(__nv_bfloat16, w1xl, g_w1x_lo);
    SYM(float, b0, g_b0);               SYM(float, b1, g_b1);
    SYM(__nv_bfloat16, xph, g_xp_hi);   SYM(__nv_bfloat16, xpl, g_xp_lo);
    #undef SYM

    prep_weights<<<256, 256>>>(w_hh0, w_ih0, w_hh1, w_ih1, b_ih0, b_hh0, b_ih1, b_hh1);
    prep_x<<<2048, 256>>>(x);
    zero_state_kernel<<<512, 256>>>();

    dim3 grid(NB / 128, 1024 / 128);  // (32, 8)
    for (int t = 0; t < T_STEPS; t++){
        long pi = (t & 1) * (long)BH;
        long po = ((t + 1) & 1) * (long)BH;
        // Layer 0: A1 = h0 (4 chunks of K=64... K=256), A2 = x_t padded (1 chunk, K=64)
        lstm_step_mma<<<grid, 256, SMEM_DYN>>>(
            h0hi + pi, h0lo + pi, 4,
            xph + (long)t * NB * XK, xpl + (long)t * NB * XK, 1, XK,
            w0h, w0l, wx0h, wx0l, XK,
            b0, c0, h0hi + po, h0lo + po, (float*)0);
        // Layer 1: A1 = h1 (4 chunks), A2 = h0_out of this step (4 chunks)
        lstm_step_mma<<<grid, 256, SMEM_DYN>>>(
            h1hi + pi, h1lo + pi, 4,
            h0hi + po, h0lo + po, 4, HDIM,
            w1hh, w1hl, w1xh, w1xl, HDIM,
            b1, c1, h1hi + po, h1lo + po, h1f);
    }

    final_kernel<<<NB / 256, 256>>>(h1f, fc_w, fc_b, x, out);
}